// round 14
// baseline (speedup 1.0000x reference)
#include <cuda_runtime.h>
#include <cuda_fp16.h>
#include <math.h>
#include <stdint.h>

#define BATCH 4096

// ---------------------------------------------------------------- PTX helpers
__device__ __forceinline__ uint32_t smem_u32(const void* p) {
    uint32_t a;
    asm("{ .reg .u64 t; cvta.to.shared.u64 t, %1; cvt.u32.u64 %0, t; }" : "=r"(a) : "l"(p));
    return a;
}
__device__ __forceinline__ void cp16(uint32_t s, const void* g) {
    asm volatile("cp.async.cg.shared.global [%0], [%1], 16;" :: "r"(s), "l"(g));
}
__device__ __forceinline__ void cp_commit() { asm volatile("cp.async.commit_group;" ::: "memory"); }
__device__ __forceinline__ void cp_wait1() { asm volatile("cp.async.wait_group 1;" ::: "memory"); }

__device__ __forceinline__ void ldsm_x4(uint32_t* r, uint32_t addr) {
    asm volatile("ldmatrix.sync.aligned.m8n8.x4.shared.b16 {%0,%1,%2,%3}, [%4];"
                 : "=r"(r[0]), "=r"(r[1]), "=r"(r[2]), "=r"(r[3]) : "r"(addr));
}
__device__ __forceinline__ void ldsm_x4t(uint32_t* r, uint32_t addr) {
    asm volatile("ldmatrix.sync.aligned.m8n8.x4.trans.shared.b16 {%0,%1,%2,%3}, [%4];"
                 : "=r"(r[0]), "=r"(r[1]), "=r"(r[2]), "=r"(r[3]) : "r"(addr));
}
__device__ __forceinline__ void mma_f16(float* c, const uint32_t* a, const uint32_t* b) {
    asm volatile(
        "mma.sync.aligned.m16n8k16.row.col.f32.f16.f16.f32 "
        "{%0,%1,%2,%3}, {%4,%5,%6,%7}, {%8,%9}, {%0,%1,%2,%3};"
        : "+f"(c[0]), "+f"(c[1]), "+f"(c[2]), "+f"(c[3])
        : "r"(a[0]), "r"(a[1]), "r"(a[2]), "r"(a[3]), "r"(b[0]), "r"(b[1]));
}

// ---------------------------------------------------------------- scratch
// activation planes (fp16 row-major), elem offsets
#define X_OFF   0u
#define H1_OFF  10485760u
#define H2_OFF  14680064u
#define MS_OFF  16777216u   // 4096 x 64 (K padded 24 -> 64)
#define D1_OFF  17039360u
#define D2_OFF  17563648u
#define D3_OFF  18612224u
#define D4_OFF  20709376u
#define ACT_TOTAL 24903680u
// weight planes (fp16 row-major (Kp, N)), K padded to mult of 64 for W4
#define W1_OFF  0u
#define W2_OFF  2621440u
#define W3_OFF  3145728u
#define W4_OFF  3276800u    // 64 x 128
#define W5_OFF  3284992u
#define W6_OFF  3317760u
#define W7_OFF  3448832u
#define W8_OFF  3973120u
#define WT_TOTAL 6594560u

__device__ __align__(16) __half g_act[ACT_TOTAL];
__device__ __align__(16) __half g_wt[WT_TOTAL];
__device__ float g_enc[BATCH * 256];

// ---------------------------------------------------------------- conversions
__global__ void conv_x4(const float* __restrict__ in, __half* __restrict__ o) {
    uint32_t i = (blockIdx.x * 256u + threadIdx.x) * 4u;
    float4 v = *reinterpret_cast<const float4*>(in + i);
    __half h[4];
    h[0] = __float2half(v.x);
    h[1] = __float2half(v.y);
    h[2] = __float2half(v.z);
    h[3] = __float2half(v.w);
    *reinterpret_cast<uint2*>(o + i) = *reinterpret_cast<uint2*>(h);
}

struct WSeg { const float* src; uint32_t off; uint32_t N; uint32_t Kreal; };
struct WTable { WSeg s[8]; };

__global__ void conv_w_all(WTable t, __half* __restrict__ w) {
    uint32_t idx = blockIdx.x * 256u + threadIdx.x;
    int s = 0;
#pragma unroll
    for (int j = 1; j < 8; j++)
        if (idx >= t.s[j].off) s = j;
    const WSeg seg = t.s[s];
    uint32_t i = idx - seg.off;
    uint32_t k = i / seg.N, n = i % seg.N;
    float v = (k < seg.Kreal) ? seg.src[(size_t)k * seg.N + n] : 0.0f;
    w[idx] = __float2half(v);
}

// ---------------------------------------------------------------- mma.sync GEMM
// 256 threads, 8 warps (2 in M x 4 in N). CTA tile (32*MT) x 128, BK = 64.
// A, B single fp16 planes, fp32 accumulate. 3-stage cp.async pipeline.
// A smem row = 144 B (128 data + 16 pad), B smem row = 272 B -> conflict-free ldsm.
template <int MT>
__global__ void __launch_bounds__(256, 2)
gemm_mma(const __half* __restrict__ A, const __half* __restrict__ B,
         const float* __restrict__ bias, float* __restrict__ outf,
         __half* __restrict__ O,
         int N, int Kp, int act) {
    constexpr uint32_t BM = 32u * MT;
    constexpr uint32_t A_PLANE = BM * 144u;
    constexpr uint32_t B_PLANE = 64u * 272u;     // 17408
    constexpr uint32_t STAGE = A_PLANE + B_PLANE;

    extern __shared__ char smem[];
    const uint32_t sb = smem_u32(smem);
    const int tid = threadIdx.x;
    const int lane = tid & 31, warp = tid >> 5;
    const int wm = warp & 1, wn = warp >> 1;
    const int mblock = blockIdx.y, nblock = blockIdx.x;
    const int Kc = Kp >> 6;

    auto issue = [&](int c, int s) {
        const uint32_t st_ = sb + (uint32_t)s * STAGE;
        const int k0_ = c << 6;
        // A: BM rows x 8 chunks of 16B
#pragma unroll
        for (int i = tid; i < (int)(BM * 8); i += 256) {
            int row = i >> 3, kc = i & 7;
            size_t go = (size_t)(mblock * BM + row) * Kp + k0_ + kc * 8;
            uint32_t so = st_ + row * 144 + kc * 16;
            cp16(so, A + go);
        }
        // B: 64 rows x 16 chunks of 16B
#pragma unroll
        for (int j = 0; j < 4; j++) {
            int i = tid + j * 256;
            int row = i >> 4, nc = i & 15;
            size_t go = (size_t)(k0_ + row) * N + nblock * 128 + nc * 8;
            uint32_t so = st_ + A_PLANE + row * 272 + nc * 16;
            cp16(so, B + go);
        }
    };

    issue(0, 0);
    cp_commit();
    if (Kc > 1) issue(1, 1);
    cp_commit();

    float acc[MT][4][4];
#pragma unroll
    for (int mt = 0; mt < MT; mt++)
#pragma unroll
        for (int nt = 0; nt < 4; nt++)
#pragma unroll
            for (int t = 0; t < 4; t++) acc[mt][nt][t] = 0.0f;

    for (int c = 0; c < Kc; c++) {
        cp_wait1();
        __syncthreads();
        if (c + 2 < Kc) issue(c + 2, (c + 2) % 3);
        cp_commit();

        const uint32_t st = sb + (uint32_t)(c % 3) * STAGE;
#pragma unroll
        for (int kk = 0; kk < 64; kk += 16) {
            uint32_t bf[4][2];
#pragma unroll
            for (int np = 0; np < 2; np++) {
                int row = kk + (lane & 15);
                int nc = ((wn * 32 + np * 16) >> 3) + (lane >> 4);
                uint32_t bd = st + A_PLANE + row * 272 + nc * 16;
                uint32_t r[4];
                ldsm_x4t(r, bd);
                bf[np * 2][0] = r[0]; bf[np * 2][1] = r[1];
                bf[np * 2 + 1][0] = r[2]; bf[np * 2 + 1][1] = r[3];
            }
#pragma unroll
            for (int mt = 0; mt < MT; mt++) {
                int row = wm * (16 * MT) + mt * 16 + (lane & 15);
                int kc = (kk >> 3) + (lane >> 4);
                uint32_t ad = st + row * 144 + kc * 16;
                uint32_t af[4];
                ldsm_x4(af, ad);
#pragma unroll
                for (int nt = 0; nt < 4; nt++)
                    mma_f16(acc[mt][nt], af, bf[nt]);
            }
        }
    }

    // ---------------- epilogue ----------------
#pragma unroll
    for (int mt = 0; mt < MT; mt++) {
#pragma unroll
        for (int nt = 0; nt < 4; nt++) {
            const int r0 = mblock * BM + wm * (16 * MT) + mt * 16 + (lane >> 2);
            const int cc = nblock * 128 + wn * 32 + nt * 8 + (lane & 3) * 2;
            const float2 bv = *reinterpret_cast<const float2*>(&bias[cc]);
            float v[4];
            v[0] = acc[mt][nt][0] + bv.x;
            v[1] = acc[mt][nt][1] + bv.y;
            v[2] = acc[mt][nt][2] + bv.x;
            v[3] = acc[mt][nt][3] + bv.y;
#pragma unroll
            for (int t = 0; t < 4; t++)
                v[t] = (act == 1) ? (v[t] >= 0.0f ? v[t] : 0.2f * v[t]) : tanhf(v[t]);
            if (outf) {
                *reinterpret_cast<float2*>(&outf[(size_t)r0 * N + cc]) = make_float2(v[0], v[1]);
                *reinterpret_cast<float2*>(&outf[(size_t)(r0 + 8) * N + cc]) = make_float2(v[2], v[3]);
            } else {
#pragma unroll
                for (int rr = 0; rr < 2; rr++) {
                    __half2 hp;
                    hp.x = __float2half(v[rr * 2 + 0]);
                    hp.y = __float2half(v[rr * 2 + 1]);
                    const size_t o = (size_t)(r0 + rr * 8) * N + cc;
                    *reinterpret_cast<__half2*>(&O[o]) = hp;
                }
            }
        }
    }
}

#define SMEM_MT2 (3u * (64u * 144u + 17408u))   // 79872
#define SMEM_MT1 (3u * (32u * 144u + 17408u))   // 66048

// ---------------------------------------------------------------- quantum circuit
template <int Q>
__device__ __forceinline__ void rot_gate(float (&re)[8], float (&im)[8],
                                         float m00r, float m00i, float m01r, float m01i,
                                         float m10r, float m10i, float m11r, float m11i,
                                         int lane) {
    if constexpr (Q < 3) {
        constexpr int rm = 1 << (2 - Q);
#pragma unroll
        for (int r = 0; r < 8; r++)
            if (!(r & rm)) {
                const int p = r | rm;
                const float ar = re[r], ai = im[r], br = re[p], bi = im[p];
                re[r] = m00r * ar - m00i * ai + m01r * br - m01i * bi;
                im[r] = m00r * ai + m00i * ar + m01r * bi + m01i * br;
                re[p] = m10r * ar - m10i * ai + m11r * br - m11i * bi;
                im[p] = m10r * ai + m10i * ar + m11r * bi + m11i * br;
            }
    } else {
        constexpr int lm = 1 << (7 - Q);
        const bool hi = lane & lm;
#pragma unroll
        for (int r = 0; r < 8; r++) {
            const float pr = __shfl_xor_sync(0xffffffffu, re[r], lm);
            const float pi = __shfl_xor_sync(0xffffffffu, im[r], lm);
            const float ar = re[r], ai = im[r];
            if (!hi) {
                re[r] = m00r * ar - m00i * ai + m01r * pr - m01i * pi;
                im[r] = m00r * ai + m00i * ar + m01r * pi + m01i * pr;
            } else {
                re[r] = m10r * pr - m10i * pi + m11r * ar - m11i * ai;
                im[r] = m10r * pi + m10i * pr + m11r * ai + m11i * ar;
            }
        }
    }
}

template <int C, int T>
__device__ __forceinline__ void cnot_gate(float (&re)[8], float (&im)[8], int lane) {
    if constexpr (C < 3 && T < 3) {
        constexpr int cm = 1 << (2 - C), tm = 1 << (2 - T);
#pragma unroll
        for (int r = 0; r < 8; r++)
            if ((r & cm) && !(r & tm)) {
                const int p = r | tm;
                float t;
                t = re[r]; re[r] = re[p]; re[p] = t;
                t = im[r]; im[r] = im[p]; im[p] = t;
            }
    } else if constexpr (C < 3 && T >= 3) {
        constexpr int cm = 1 << (2 - C), tm = 1 << (7 - T);
#pragma unroll
        for (int r = 0; r < 8; r++)
            if (r & cm) {
                re[r] = __shfl_xor_sync(0xffffffffu, re[r], tm);
                im[r] = __shfl_xor_sync(0xffffffffu, im[r], tm);
            }
    } else if constexpr (C >= 3 && T < 3) {
        constexpr int cm = 1 << (7 - C), tm = 1 << (2 - T);
        const bool act = lane & cm;
#pragma unroll
        for (int r = 0; r < 8; r++)
            if (!(r & tm)) {
                const int p = r | tm;
                const float r0 = act ? re[p] : re[r];
                const float r1 = act ? re[r] : re[p];
                const float i0 = act ? im[p] : im[r];
                const float i1 = act ? im[r] : im[p];
                re[r] = r0; re[p] = r1; im[r] = i0; im[p] = i1;
            }
    } else {
        constexpr int cm = 1 << (7 - C), tm = 1 << (7 - T);
        const int src = (lane & cm) ? (lane ^ tm) : lane;
#pragma unroll
        for (int r = 0; r < 8; r++) {
            re[r] = __shfl_sync(0xffffffffu, re[r], src);
            im[r] = __shfl_sync(0xffffffffu, im[r], src);
        }
    }
}

template <int L>
__device__ __forceinline__ void do_layer(float (&re)[8], float (&im)[8],
                                         const float* __restrict__ sp, int lane) {
#define ROTG(Q) {                                                                   \
        const float phi = sp[(L * 8 + Q) * 3 + 0];                                  \
        const float th  = sp[(L * 8 + Q) * 3 + 1];                                  \
        const float om  = sp[(L * 8 + Q) * 3 + 2];                                  \
        float s, c, sa, ca, sd, cd;                                                 \
        sincosf(0.5f * th, &s, &c);                                                 \
        sincosf(0.5f * (phi + om), &sa, &ca);                                       \
        sincosf(0.5f * (phi - om), &sd, &cd);                                       \
        rot_gate<Q>(re, im, ca * c, -sa * c, -cd * s, -sd * s,                      \
                    cd * s, -sd * s, ca * c, sa * c, lane); }
    ROTG(0) ROTG(1) ROTG(2) ROTG(3) ROTG(4) ROTG(5) ROTG(6) ROTG(7)
#undef ROTG
    cnot_gate<0, (0 + L + 1) % 8>(re, im, lane);
    cnot_gate<1, (1 + L + 1) % 8>(re, im, lane);
    cnot_gate<2, (2 + L + 1) % 8>(re, im, lane);
    cnot_gate<3, (3 + L + 1) % 8>(re, im, lane);
    cnot_gate<4, (4 + L + 1) % 8>(re, im, lane);
    cnot_gate<5, (5 + L + 1) % 8>(re, im, lane);
    cnot_gate<6, (6 + L + 1) % 8>(re, im, lane);
    cnot_gate<7, (7 + L + 1) % 8>(re, im, lane);
}

template <int Q>
__device__ __forceinline__ void measure(const float (&re)[8], const float (&im)[8], int lane,
                                        float& Z, float& X, float& Y) {
    float z = 0.0f, x = 0.0f, y = 0.0f;
    if constexpr (Q < 3) {
        constexpr int rm = 1 << (2 - Q);
#pragma unroll
        for (int r = 0; r < 8; r++) {
            const float ar = re[r], ai = im[r];
            const int p = r ^ rm;
            const float br = re[p], bi = im[p];
            const float sign = (r & rm) ? -1.0f : 1.0f;
            z += sign * (ar * ar + ai * ai);
            x += ar * br + ai * bi;
            y += sign * (ar * bi - ai * br);
        }
    } else {
        constexpr int lm = 1 << (7 - Q);
        const float sign = (lane & lm) ? -1.0f : 1.0f;
#pragma unroll
        for (int r = 0; r < 8; r++) {
            const float ar = re[r], ai = im[r];
            const float br = __shfl_xor_sync(0xffffffffu, ar, lm);
            const float bi = __shfl_xor_sync(0xffffffffu, ai, lm);
            z += sign * (ar * ar + ai * ai);
            x += ar * br + ai * bi;
            y += sign * (ar * bi - ai * br);
        }
    }
#pragma unroll
    for (int o = 16; o > 0; o >>= 1) {
        z += __shfl_xor_sync(0xffffffffu, z, o);
        x += __shfl_xor_sync(0xffffffffu, x, o);
        y += __shfl_xor_sync(0xffffffffu, y, o);
    }
    Z = z; X = x; Y = y;
}

__global__ void __launch_bounds__(256)
quantum_kernel(const float* __restrict__ enc, const float* __restrict__ params,
               __half* __restrict__ mh) {
    __shared__ float sp[144];
    __shared__ float sm[8][32];

    const int tid = threadIdx.x;
    const int lane = tid & 31, w = tid >> 5;
    if (tid < 144) sp[tid] = params[tid];
    __syncthreads();

    const int row = blockIdx.x * 8 + w;

    float re[8], im[8];
    float ss = 0.0f;
#pragma unroll
    for (int r = 0; r < 8; r++) {
        const float v = enc[(size_t)row * 256 + r * 32 + lane];
        re[r] = v; im[r] = 0.0f;
        ss += v * v;
    }
#pragma unroll
    for (int o = 16; o > 0; o >>= 1) ss += __shfl_xor_sync(0xffffffffu, ss, o);
    const float inv = 1.0f / fmaxf(sqrtf(ss), 1e-12f);
#pragma unroll
    for (int r = 0; r < 8; r++) re[r] *= inv;

    do_layer<0>(re, im, sp, lane);
    do_layer<1>(re, im, sp, lane);
    do_layer<2>(re, im, sp, lane);
    do_layer<3>(re, im, sp, lane);
    do_layer<4>(re, im, sp, lane);
    do_layer<5>(re, im, sp, lane);

#define MEAS(Q) {                                                   \
        float Z, X, Y;                                              \
        measure<Q>(re, im, lane, Z, X, Y);                          \
        if (lane == 0) { sm[w][Q] = Z; sm[w][8 + Q] = X; sm[w][16 + Q] = Y; } }
    MEAS(0) MEAS(1) MEAS(2) MEAS(3) MEAS(4) MEAS(5) MEAS(6) MEAS(7)
#undef MEAS
    __syncwarp();

    // meas row is 64 wide (K padded to 64); lanes write cols [0,32) and [32,64)
    const float mv = (lane < 24) ? sm[w][lane] : 0.0f;
    mh[(size_t)row * 64 + lane] = __float2half(mv);
    mh[(size_t)row * 64 + 32 + lane] = __float2half(0.0f);
}

// ---------------------------------------------------------------- launch
extern "C" void kernel_launch(void* const* d_in, const int* in_sizes, int n_in,
                              void* d_out, int out_size) {
    const float* x          = (const float*)d_in[0];
    const float* ew1        = (const float*)d_in[1];
    const float* eb1        = (const float*)d_in[2];
    const float* ew2        = (const float*)d_in[3];
    const float* eb2        = (const float*)d_in[4];
    const float* ew3        = (const float*)d_in[5];
    const float* eb3        = (const float*)d_in[6];
    const float* dec_params = (const float*)d_in[7];
    const float* dw1        = (const float*)d_in[8];
    const float* db1        = (const float*)d_in[9];
    const float* dw2        = (const float*)d_in[10];
    const float* db2        = (const float*)d_in[11];
    const float* dw3        = (const float*)d_in[12];
    const float* db3        = (const float*)d_in[13];
    const float* dw4        = (const float*)d_in[14];
    const float* db4        = (const float*)d_in[15];
    const float* dw5        = (const float*)d_in[16];
    const float* db5        = (const float*)d_in[17];
    float* out = (float*)d_out;

    __half *a_, *wt_;
    float* enc;
    cudaGetSymbolAddress((void**)&a_, g_act);
    cudaGetSymbolAddress((void**)&wt_, g_wt);
    cudaGetSymbolAddress((void**)&enc, g_enc);

    cudaFuncSetAttribute(gemm_mma<2>, cudaFuncAttributeMaxDynamicSharedMemorySize, SMEM_MT2);
    cudaFuncSetAttribute(gemm_mma<1>, cudaFuncAttributeMaxDynamicSharedMemorySize, SMEM_MT1);

    // ---- conversions ----
    conv_x4<<<(BATCH * 2560) / 1024, 256>>>(x, a_ + X_OFF);
    WTable wt;
    wt.s[0] = {ew1, W1_OFF, 1024, 2560};
    wt.s[1] = {ew2, W2_OFF, 512, 1024};
    wt.s[2] = {ew3, W3_OFF, 256, 512};
    wt.s[3] = {dw1, W4_OFF, 128, 24};
    wt.s[4] = {dw2, W5_OFF, 256, 128};
    wt.s[5] = {dw3, W6_OFF, 512, 256};
    wt.s[6] = {dw4, W7_OFF, 1024, 512};
    wt.s[7] = {dw5, W8_OFF, 2560, 1024};
    conv_w_all<<<WT_TOTAL / 256, 256>>>(wt, wt_);

    // ---- encoder ----
    gemm_mma<2><<<dim3(8, 64), 256, SMEM_MT2>>>(a_ + X_OFF, wt_ + W1_OFF,
                                                eb1, nullptr, a_ + H1_OFF, 1024, 2560, 1);
    gemm_mma<2><<<dim3(4, 64), 256, SMEM_MT2>>>(a_ + H1_OFF, wt_ + W2_OFF,
                                                eb2, nullptr, a_ + H2_OFF, 512, 1024, 1);
    gemm_mma<2><<<dim3(2, 64), 256, SMEM_MT2>>>(a_ + H2_OFF, wt_ + W3_OFF,
                                                eb3, enc, nullptr, 256, 512, 2);

    // ---- quantum (one warp per row) ----
    quantum_kernel<<<BATCH / 8, 256>>>(enc, dec_params, a_ + MS_OFF);

    // ---- decoder ----
    gemm_mma<1><<<dim3(1, 128), 256, SMEM_MT1>>>(a_ + MS_OFF, wt_ + W4_OFF,
                                                 db1, nullptr, a_ + D1_OFF, 128, 64, 1);
    gemm_mma<2><<<dim3(2, 64), 256, SMEM_MT2>>>(a_ + D1_OFF, wt_ + W5_OFF,
                                                db2, nullptr, a_ + D2_OFF, 256, 128, 1);
    gemm_mma<2><<<dim3(4, 64), 256, SMEM_MT2>>>(a_ + D2_OFF, wt_ + W6_OFF,
                                                db3, nullptr, a_ + D3_OFF, 512, 256, 1);
    gemm_mma<2><<<dim3(8, 64), 256, SMEM_MT2>>>(a_ + D3_OFF, wt_ + W7_OFF,
                                                db4, nullptr, a_ + D4_OFF, 1024, 512, 1);
    gemm_mma<2><<<dim3(20, 64), 256, SMEM_MT2>>>(a_ + D4_OFF, wt_ + W8_OFF,
                                                 db5, out, nullptr, 2560, 1024, 2);
}

// round 15
// speedup vs baseline: 1.0187x; 1.0187x over previous
#include <cuda_runtime.h>
#include <cuda_fp16.h>
#include <math.h>
#include <stdint.h>

#define BATCH 4096

// ---------------------------------------------------------------- PTX helpers
__device__ __forceinline__ uint32_t smem_u32(const void* p) {
    uint32_t a;
    asm("{ .reg .u64 t; cvta.to.shared.u64 t, %1; cvt.u32.u64 %0, t; }" : "=r"(a) : "l"(p));
    return a;
}
__device__ __forceinline__ void cp16(uint32_t s, const void* g) {
    asm volatile("cp.async.cg.shared.global [%0], [%1], 16;" :: "r"(s), "l"(g));
}
__device__ __forceinline__ void cp_commit() { asm volatile("cp.async.commit_group;" ::: "memory"); }
__device__ __forceinline__ void cp_wait1() { asm volatile("cp.async.wait_group 1;" ::: "memory"); }

__device__ __forceinline__ void ldsm_x4(uint32_t* r, uint32_t addr) {
    asm volatile("ldmatrix.sync.aligned.m8n8.x4.shared.b16 {%0,%1,%2,%3}, [%4];"
                 : "=r"(r[0]), "=r"(r[1]), "=r"(r[2]), "=r"(r[3]) : "r"(addr));
}
__device__ __forceinline__ void ldsm_x4t(uint32_t* r, uint32_t addr) {
    asm volatile("ldmatrix.sync.aligned.m8n8.x4.trans.shared.b16 {%0,%1,%2,%3}, [%4];"
                 : "=r"(r[0]), "=r"(r[1]), "=r"(r[2]), "=r"(r[3]) : "r"(addr));
}
__device__ __forceinline__ void mma_f16(float* c, const uint32_t* a, const uint32_t* b) {
    asm volatile(
        "mma.sync.aligned.m16n8k16.row.col.f32.f16.f16.f32 "
        "{%0,%1,%2,%3}, {%4,%5,%6,%7}, {%8,%9}, {%0,%1,%2,%3};"
        : "+f"(c[0]), "+f"(c[1]), "+f"(c[2]), "+f"(c[3])
        : "r"(a[0]), "r"(a[1]), "r"(a[2]), "r"(a[3]), "r"(b[0]), "r"(b[1]));
}

// ---------------------------------------------------------------- scratch
#define X_OFF   0u
#define H1_OFF  10485760u
#define H2_OFF  14680064u
#define MS_OFF  16777216u
#define D1_OFF  16908288u
#define D2_OFF  17432576u
#define D3_OFF  18481152u
#define D4_OFF  20578304u
#define ACT_TOTAL 24772608u
#define W1_OFF  0u
#define W2_OFF  2621440u
#define W3_OFF  3145728u
#define W4_OFF  3276800u
#define W5_OFF  3280896u
#define W6_OFF  3313664u
#define W7_OFF  3444736u
#define W8_OFF  3969024u
#define WT_TOTAL 6590464u

__device__ __align__(16) __half g_act[ACT_TOTAL];
__device__ __align__(16) __half g_wt[WT_TOTAL];
__device__ float g_enc[BATCH * 256];

// ---------------------------------------------------------------- conversions
__global__ void conv_x4(const float* __restrict__ in, __half* __restrict__ o) {
    uint32_t i = (blockIdx.x * 256u + threadIdx.x) * 4u;
    float4 v = *reinterpret_cast<const float4*>(in + i);
    __half h[4];
    h[0] = __float2half(v.x);
    h[1] = __float2half(v.y);
    h[2] = __float2half(v.z);
    h[3] = __float2half(v.w);
    *reinterpret_cast<uint2*>(o + i) = *reinterpret_cast<uint2*>(h);
}

struct WSeg { const float* src; uint32_t off; uint32_t N; uint32_t Kreal; };
struct WTable { WSeg s[8]; };

__global__ void conv_w_all(WTable t, __half* __restrict__ w) {
    uint32_t idx = blockIdx.x * 256u + threadIdx.x;
    int s = 0;
#pragma unroll
    for (int j = 1; j < 8; j++)
        if (idx >= t.s[j].off) s = j;
    const WSeg seg = t.s[s];
    uint32_t i = idx - seg.off;
    uint32_t k = i / seg.N, n = i % seg.N;
    float v = (k < seg.Kreal) ? seg.src[(size_t)k * seg.N + n] : 0.0f;
    w[idx] = __float2half(v);
}

// ---------------------------------------------------------------- mma.sync GEMM
// 256 threads, 8 warps (2 in M x 4 in N). CTA tile (32*MT) x 128, BK = 32.
// A, B single fp16 planes, fp32 accumulate. 3-stage cp.async pipeline.
// MT4 (warp tile 64x32) maximizes fragment reuse (262 B smem/MMA vs 400 at MT2)
// for big-N layers; MT2/MT1 keep CTA counts high for narrow layers.
template <int MT>
__global__ void __launch_bounds__(256, 2)
gemm_mma(const __half* __restrict__ A, const __half* __restrict__ B,
         const float* __restrict__ bias, float* __restrict__ outf,
         __half* __restrict__ O,
         int N, int Kp, int act) {
    constexpr uint32_t BM = 32u * MT;
    constexpr uint32_t A_PLANE = BM * 80u;
    constexpr uint32_t B_PLANE = 8704u;      // 32 rows * 272 B
    constexpr uint32_t STAGE = A_PLANE + B_PLANE;

    extern __shared__ char smem[];
    const uint32_t sb = smem_u32(smem);
    const int tid = threadIdx.x;
    const int lane = tid & 31, warp = tid >> 5;
    const int wm = warp & 1, wn = warp >> 1;
    const int mblock = blockIdx.y, nblock = blockIdx.x;
    const int Kc = Kp >> 5;

    auto issue = [&](int c, int s) {
        const uint32_t st_ = sb + (uint32_t)s * STAGE;
        const int k0_ = c << 5;
#pragma unroll
        for (int i = tid; i < (int)(BM * 4); i += 256) {
            int row = i >> 2, kc = i & 3;
            size_t go = (size_t)(mblock * BM + row) * Kp + k0_ + kc * 8;
            uint32_t so = st_ + row * 80 + kc * 16;
            cp16(so, A + go);
        }
#pragma unroll
        for (int j = 0; j < 2; j++) {
            int i = tid + j * 256;
            int row = i >> 4, nc = i & 15;
            size_t go = (size_t)(k0_ + row) * N + nblock * 128 + nc * 8;
            uint32_t so = st_ + A_PLANE + row * 272 + nc * 16;
            cp16(so, B + go);
        }
    };

    issue(0, 0);
    cp_commit();
    if (Kc > 1) issue(1, 1);
    cp_commit();

    float acc[MT][4][4];
#pragma unroll
    for (int mt = 0; mt < MT; mt++)
#pragma unroll
        for (int nt = 0; nt < 4; nt++)
#pragma unroll
            for (int t = 0; t < 4; t++) acc[mt][nt][t] = 0.0f;

    for (int c = 0; c < Kc; c++) {
        cp_wait1();
        __syncthreads();
        if (c + 2 < Kc) issue(c + 2, (c + 2) % 3);
        cp_commit();

        const uint32_t st = sb + (uint32_t)(c % 3) * STAGE;
#pragma unroll
        for (int kk = 0; kk < 32; kk += 16) {
            uint32_t bf[4][2];
#pragma unroll
            for (int np = 0; np < 2; np++) {
                int row = kk + (lane & 15);
                int nc = ((wn * 32 + np * 16) >> 3) + (lane >> 4);
                uint32_t bd = st + A_PLANE + row * 272 + nc * 16;
                uint32_t r[4];
                ldsm_x4t(r, bd);
                bf[np * 2][0] = r[0]; bf[np * 2][1] = r[1];
                bf[np * 2 + 1][0] = r[2]; bf[np * 2 + 1][1] = r[3];
            }
#pragma unroll
            for (int mt = 0; mt < MT; mt++) {
                int row = wm * (16 * MT) + mt * 16 + (lane & 15);
                int kc = (kk >> 3) + (lane >> 4);
                uint32_t ad = st + row * 80 + kc * 16;
                uint32_t af[4];
                ldsm_x4(af, ad);
#pragma unroll
                for (int nt = 0; nt < 4; nt++)
                    mma_f16(acc[mt][nt], af, bf[nt]);
            }
        }
    }

    // ---------------- epilogue ----------------
#pragma unroll
    for (int mt = 0; mt < MT; mt++) {
#pragma unroll
        for (int nt = 0; nt < 4; nt++) {
            const int r0 = mblock * BM + wm * (16 * MT) + mt * 16 + (lane >> 2);
            const int cc = nblock * 128 + wn * 32 + nt * 8 + (lane & 3) * 2;
            const float2 bv = *reinterpret_cast<const float2*>(&bias[cc]);
            float v[4];
            v[0] = acc[mt][nt][0] + bv.x;
            v[1] = acc[mt][nt][1] + bv.y;
            v[2] = acc[mt][nt][2] + bv.x;
            v[3] = acc[mt][nt][3] + bv.y;
#pragma unroll
            for (int t = 0; t < 4; t++)
                v[t] = (act == 1) ? (v[t] >= 0.0f ? v[t] : 0.2f * v[t]) : tanhf(v[t]);
            if (outf) {
                *reinterpret_cast<float2*>(&outf[(size_t)r0 * N + cc]) = make_float2(v[0], v[1]);
                *reinterpret_cast<float2*>(&outf[(size_t)(r0 + 8) * N + cc]) = make_float2(v[2], v[3]);
            } else {
#pragma unroll
                for (int rr = 0; rr < 2; rr++) {
                    __half2 hp;
                    hp.x = __float2half(v[rr * 2 + 0]);
                    hp.y = __float2half(v[rr * 2 + 1]);
                    const size_t o = (size_t)(r0 + rr * 8) * N + cc;
                    *reinterpret_cast<__half2*>(&O[o]) = hp;
                }
            }
        }
    }
}

#define SMEM_MT4 (3u * (128u * 80u + 8704u))   // 56832
#define SMEM_MT2 (3u * (64u * 80u + 8704u))    // 41472
#define SMEM_MT1 (3u * (32u * 80u + 8704u))    // 33792

// ---------------------------------------------------------------- quantum circuit
template <int Q>
__device__ __forceinline__ void rot_gate(float (&re)[8], float (&im)[8],
                                         float m00r, float m00i, float m01r, float m01i,
                                         float m10r, float m10i, float m11r, float m11i,
                                         int lane) {
    if constexpr (Q < 3) {
        constexpr int rm = 1 << (2 - Q);
#pragma unroll
        for (int r = 0; r < 8; r++)
            if (!(r & rm)) {
                const int p = r | rm;
                const float ar = re[r], ai = im[r], br = re[p], bi = im[p];
                re[r] = m00r * ar - m00i * ai + m01r * br - m01i * bi;
                im[r] = m00r * ai + m00i * ar + m01r * bi + m01i * br;
                re[p] = m10r * ar - m10i * ai + m11r * br - m11i * bi;
                im[p] = m10r * ai + m10i * ar + m11r * bi + m11i * br;
            }
    } else {
        constexpr int lm = 1 << (7 - Q);
        const bool hi = lane & lm;
#pragma unroll
        for (int r = 0; r < 8; r++) {
            const float pr = __shfl_xor_sync(0xffffffffu, re[r], lm);
            const float pi = __shfl_xor_sync(0xffffffffu, im[r], lm);
            const float ar = re[r], ai = im[r];
            if (!hi) {
                re[r] = m00r * ar - m00i * ai + m01r * pr - m01i * pi;
                im[r] = m00r * ai + m00i * ar + m01r * pi + m01i * pr;
            } else {
                re[r] = m10r * pr - m10i * pi + m11r * ar - m11i * ai;
                im[r] = m10r * pi + m10i * pr + m11r * ai + m11i * ar;
            }
        }
    }
}

template <int C, int T>
__device__ __forceinline__ void cnot_gate(float (&re)[8], float (&im)[8], int lane) {
    if constexpr (C < 3 && T < 3) {
        constexpr int cm = 1 << (2 - C), tm = 1 << (2 - T);
#pragma unroll
        for (int r = 0; r < 8; r++)
            if ((r & cm) && !(r & tm)) {
                const int p = r | tm;
                float t;
                t = re[r]; re[r] = re[p]; re[p] = t;
                t = im[r]; im[r] = im[p]; im[p] = t;
            }
    } else if constexpr (C < 3 && T >= 3) {
        constexpr int cm = 1 << (2 - C), tm = 1 << (7 - T);
#pragma unroll
        for (int r = 0; r < 8; r++)
            if (r & cm) {
                re[r] = __shfl_xor_sync(0xffffffffu, re[r], tm);
                im[r] = __shfl_xor_sync(0xffffffffu, im[r], tm);
            }
    } else if constexpr (C >= 3 && T < 3) {
        constexpr int cm = 1 << (7 - C), tm = 1 << (2 - T);
        const bool act = lane & cm;
#pragma unroll
        for (int r = 0; r < 8; r++)
            if (!(r & tm)) {
                const int p = r | tm;
                const float r0 = act ? re[p] : re[r];
                const float r1 = act ? re[r] : re[p];
                const float i0 = act ? im[p] : im[r];
                const float i1 = act ? im[r] : im[p];
                re[r] = r0; re[p] = r1; im[r] = i0; im[p] = i1;
            }
    } else {
        constexpr int cm = 1 << (7 - C), tm = 1 << (7 - T);
        const int src = (lane & cm) ? (lane ^ tm) : lane;
#pragma unroll
        for (int r = 0; r < 8; r++) {
            re[r] = __shfl_sync(0xffffffffu, re[r], src);
            im[r] = __shfl_sync(0xffffffffu, im[r], src);
        }
    }
}

template <int L>
__device__ __forceinline__ void do_layer(float (&re)[8], float (&im)[8],
                                         const float* __restrict__ sp, int lane) {
#define ROTG(Q) {                                                                   \
        const float phi = sp[(L * 8 + Q) * 3 + 0];                                  \
        const float th  = sp[(L * 8 + Q) * 3 + 1];                                  \
        const float om  = sp[(L * 8 + Q) * 3 + 2];                                  \
        float s, c, sa, ca, sd, cd;                                                 \
        sincosf(0.5f * th, &s, &c);                                                 \
        sincosf(0.5f * (phi + om), &sa, &ca);                                       \
        sincosf(0.5f * (phi - om), &sd, &cd);                                       \
        rot_gate<Q>(re, im, ca * c, -sa * c, -cd * s, -sd * s,                      \
                    cd * s, -sd * s, ca * c, sa * c, lane); }
    ROTG(0) ROTG(1) ROTG(2) ROTG(3) ROTG(4) ROTG(5) ROTG(6) ROTG(7)
#undef ROTG
    cnot_gate<0, (0 + L + 1) % 8>(re, im, lane);
    cnot_gate<1, (1 + L + 1) % 8>(re, im, lane);
    cnot_gate<2, (2 + L + 1) % 8>(re, im, lane);
    cnot_gate<3, (3 + L + 1) % 8>(re, im, lane);
    cnot_gate<4, (4 + L + 1) % 8>(re, im, lane);
    cnot_gate<5, (5 + L + 1) % 8>(re, im, lane);
    cnot_gate<6, (6 + L + 1) % 8>(re, im, lane);
    cnot_gate<7, (7 + L + 1) % 8>(re, im, lane);
}

template <int Q>
__device__ __forceinline__ void measure(const float (&re)[8], const float (&im)[8], int lane,
                                        float& Z, float& X, float& Y) {
    float z = 0.0f, x = 0.0f, y = 0.0f;
    if constexpr (Q < 3) {
        constexpr int rm = 1 << (2 - Q);
#pragma unroll
        for (int r = 0; r < 8; r++) {
            const float ar = re[r], ai = im[r];
            const int p = r ^ rm;
            const float br = re[p], bi = im[p];
            const float sign = (r & rm) ? -1.0f : 1.0f;
            z += sign * (ar * ar + ai * ai);
            x += ar * br + ai * bi;
            y += sign * (ar * bi - ai * br);
        }
    } else {
        constexpr int lm = 1 << (7 - Q);
        const float sign = (lane & lm) ? -1.0f : 1.0f;
#pragma unroll
        for (int r = 0; r < 8; r++) {
            const float ar = re[r], ai = im[r];
            const float br = __shfl_xor_sync(0xffffffffu, ar, lm);
            const float bi = __shfl_xor_sync(0xffffffffu, ai, lm);
            z += sign * (ar * ar + ai * ai);
            x += ar * br + ai * bi;
            y += sign * (ar * bi - ai * br);
        }
    }
#pragma unroll
    for (int o = 16; o > 0; o >>= 1) {
        z += __shfl_xor_sync(0xffffffffu, z, o);
        x += __shfl_xor_sync(0xffffffffu, x, o);
        y += __shfl_xor_sync(0xffffffffu, y, o);
    }
    Z = z; X = x; Y = y;
}

__global__ void __launch_bounds__(256)
quantum_kernel(const float* __restrict__ enc, const float* __restrict__ params,
               __half* __restrict__ mh) {
    __shared__ float sp[144];
    __shared__ float sm[8][32];

    const int tid = threadIdx.x;
    const int lane = tid & 31, w = tid >> 5;
    if (tid < 144) sp[tid] = params[tid];
    __syncthreads();

    const int row = blockIdx.x * 8 + w;

    float re[8], im[8];
    float ss = 0.0f;
#pragma unroll
    for (int r = 0; r < 8; r++) {
        const float v = enc[(size_t)row * 256 + r * 32 + lane];
        re[r] = v; im[r] = 0.0f;
        ss += v * v;
    }
#pragma unroll
    for (int o = 16; o > 0; o >>= 1) ss += __shfl_xor_sync(0xffffffffu, ss, o);
    const float inv = 1.0f / fmaxf(sqrtf(ss), 1e-12f);
#pragma unroll
    for (int r = 0; r < 8; r++) re[r] *= inv;

    do_layer<0>(re, im, sp, lane);
    do_layer<1>(re, im, sp, lane);
    do_layer<2>(re, im, sp, lane);
    do_layer<3>(re, im, sp, lane);
    do_layer<4>(re, im, sp, lane);
    do_layer<5>(re, im, sp, lane);

#define MEAS(Q) {                                                   \
        float Z, X, Y;                                              \
        measure<Q>(re, im, lane, Z, X, Y);                          \
        if (lane == 0) { sm[w][Q] = Z; sm[w][8 + Q] = X; sm[w][16 + Q] = Y; } }
    MEAS(0) MEAS(1) MEAS(2) MEAS(3) MEAS(4) MEAS(5) MEAS(6) MEAS(7)
#undef MEAS
    __syncwarp();

    const float mv = (lane < 24) ? sm[w][lane] : 0.0f;
    mh[(size_t)row * 32 + lane] = __float2half(mv);
}

// ---------------------------------------------------------------- launch
extern "C" void kernel_launch(void* const* d_in, const int* in_sizes, int n_in,
                              void* d_out, int out_size) {
    const float* x          = (const float*)d_in[0];
    const float* ew1        = (const float*)d_in[1];
    const float* eb1        = (const float*)d_in[2];
    const float* ew2        = (const float*)d_in[3];
    const float* eb2        = (const float*)d_in[4];
    const float* ew3        = (const float*)d_in[5];
    const float* eb3        = (const float*)d_in[6];
    const float* dec_params = (const float*)d_in[7];
    const float* dw1        = (const float*)d_in[8];
    const float* db1        = (const float*)d_in[9];
    const float* dw2        = (const float*)d_in[10];
    const float* db2        = (const float*)d_in[11];
    const float* dw3        = (const float*)d_in[12];
    const float* db3        = (const float*)d_in[13];
    const float* dw4        = (const float*)d_in[14];
    const float* db4        = (const float*)d_in[15];
    const float* dw5        = (const float*)d_in[16];
    const float* db5        = (const float*)d_in[17];
    float* out = (float*)d_out;

    __half *a_, *wt_;
    float* enc;
    cudaGetSymbolAddress((void**)&a_, g_act);
    cudaGetSymbolAddress((void**)&wt_, g_wt);
    cudaGetSymbolAddress((void**)&enc, g_enc);

    cudaFuncSetAttribute(gemm_mma<4>, cudaFuncAttributeMaxDynamicSharedMemorySize, SMEM_MT4);
    cudaFuncSetAttribute(gemm_mma<2>, cudaFuncAttributeMaxDynamicSharedMemorySize, SMEM_MT2);
    cudaFuncSetAttribute(gemm_mma<1>, cudaFuncAttributeMaxDynamicSharedMemorySize, SMEM_MT1);

    // ---- conversions ----
    conv_x4<<<(BATCH * 2560) / 1024, 256>>>(x, a_ + X_OFF);
    WTable wt;
    wt.s[0] = {ew1, W1_OFF, 1024, 2560};
    wt.s[1] = {ew2, W2_OFF, 512, 1024};
    wt.s[2] = {ew3, W3_OFF, 256, 512};
    wt.s[3] = {dw1, W4_OFF, 128, 24};
    wt.s[4] = {dw2, W5_OFF, 256, 128};
    wt.s[5] = {dw3, W6_OFF, 512, 256};
    wt.s[6] = {dw4, W7_OFF, 1024, 512};
    wt.s[7] = {dw5, W8_OFF, 2560, 1024};
    conv_w_all<<<WT_TOTAL / 256, 256>>>(wt, wt_);

    // ---- encoder ----
    gemm_mma<4><<<dim3(8, 32), 256, SMEM_MT4>>>(a_ + X_OFF, wt_ + W1_OFF,
                                                eb1, nullptr, a_ + H1_OFF, 1024, 2560, 1);
    gemm_mma<2><<<dim3(4, 64), 256, SMEM_MT2>>>(a_ + H1_OFF, wt_ + W2_OFF,
                                                eb2, nullptr, a_ + H2_OFF, 512, 1024, 1);
    gemm_mma<2><<<dim3(2, 64), 256, SMEM_MT2>>>(a_ + H2_OFF, wt_ + W3_OFF,
                                                eb3, enc, nullptr, 256, 512, 2);

    // ---- quantum (one warp per row) ----
    quantum_kernel<<<BATCH / 8, 256>>>(enc, dec_params, a_ + MS_OFF);

    // ---- decoder ----
    gemm_mma<1><<<dim3(1, 128), 256, SMEM_MT1>>>(a_ + MS_OFF, wt_ + W4_OFF,
                                                 db1, nullptr, a_ + D1_OFF, 128, 32, 1);
    gemm_mma<2><<<dim3(2, 64), 256, SMEM_MT2>>>(a_ + D1_OFF, wt_ + W5_OFF,
                                                db2, nullptr, a_ + D2_OFF, 256, 128, 1);
    gemm_mma<2><<<dim3(4, 64), 256, SMEM_MT2>>>(a_ + D2_OFF, wt_ + W6_OFF,
                                                db3, nullptr, a_ + D3_OFF, 512, 256, 1);
    gemm_mma<4><<<dim3(8, 32), 256, SMEM_MT4>>>(a_ + D3_OFF, wt_ + W7_OFF,
                                                db4, nullptr, a_ + D4_OFF, 1024, 512, 1);
    gemm_mma<4><<<dim3(20, 32), 256, SMEM_MT4>>>(a_ + D4_OFF, wt_ + W8_OFF,
                                                 db5, out, nullptr, 2560, 1024, 2);
}

// round 17
// speedup vs baseline: 1.0536x; 1.0343x over previous
#include <cuda_runtime.h>
#include <cuda_fp16.h>
#include <math.h>
#include <stdint.h>

#define BATCH 4096

// ---------------------------------------------------------------- PTX helpers
__device__ __forceinline__ uint32_t smem_u32(const void* p) {
    uint32_t a;
    asm("{ .reg .u64 t; cvta.to.shared.u64 t, %1; cvt.u32.u64 %0, t; }" : "=r"(a) : "l"(p));
    return a;
}
__device__ __forceinline__ void cp16(uint32_t s, const void* g) {
    asm volatile("cp.async.cg.shared.global [%0], [%1], 16;" :: "r"(s), "l"(g));
}
__device__ __forceinline__ void cp_commit() { asm volatile("cp.async.commit_group;" ::: "memory"); }
__device__ __forceinline__ void cp_wait2() { asm volatile("cp.async.wait_group 2;" ::: "memory"); }

__device__ __forceinline__ void ldsm_x4(uint32_t* r, uint32_t addr) {
    asm volatile("ldmatrix.sync.aligned.m8n8.x4.shared.b16 {%0,%1,%2,%3}, [%4];"
                 : "=r"(r[0]), "=r"(r[1]), "=r"(r[2]), "=r"(r[3]) : "r"(addr));
}
__device__ __forceinline__ void ldsm_x4t(uint32_t* r, uint32_t addr) {
    asm volatile("ldmatrix.sync.aligned.m8n8.x4.trans.shared.b16 {%0,%1,%2,%3}, [%4];"
                 : "=r"(r[0]), "=r"(r[1]), "=r"(r[2]), "=r"(r[3]) : "r"(addr));
}
__device__ __forceinline__ void mma_f16(float* c, const uint32_t* a, const uint32_t* b) {
    asm volatile(
        "mma.sync.aligned.m16n8k16.row.col.f32.f16.f16.f32 "
        "{%0,%1,%2,%3}, {%4,%5,%6,%7}, {%8,%9}, {%0,%1,%2,%3};"
        : "+f"(c[0]), "+f"(c[1]), "+f"(c[2]), "+f"(c[3])
        : "r"(a[0]), "r"(a[1]), "r"(a[2]), "r"(a[3]), "r"(b[0]), "r"(b[1]));
}

// ---------------------------------------------------------------- scratch
#define X_OFF   0u
#define H1_OFF  10485760u
#define H2_OFF  14680064u
#define MS_OFF  16777216u
#define D1_OFF  16908288u
#define D2_OFF  17432576u
#define D3_OFF  18481152u
#define D4_OFF  20578304u
#define ACT_TOTAL 24772608u
#define W1_OFF  0u
#define W2_OFF  2621440u
#define W3_OFF  3145728u
#define W4_OFF  3276800u
#define W5_OFF  3280896u
#define W6_OFF  3313664u
#define W7_OFF  3444736u
#define W8_OFF  3969024u
#define WT_TOTAL 6590464u

__device__ __align__(16) __half g_act[ACT_TOTAL];
__device__ __align__(16) __half g_wt[WT_TOTAL];
__device__ float g_enc[BATCH * 256];

// ---------------------------------------------------------------- conversions (single launch)
#define XB 10240u   // (4096*2560)/1024
#define WB 25744u   // WT_TOTAL/256

struct WSeg { const float* src; uint32_t off; uint32_t N; uint32_t Kreal; };
struct WTable { WSeg s[8]; };

__global__ void conv_all(const float* __restrict__ x, WTable t,
                         __half* __restrict__ xo, __half* __restrict__ w) {
    if (blockIdx.x < XB) {
        uint32_t i = (blockIdx.x * 256u + threadIdx.x) * 4u;
        float4 v = *reinterpret_cast<const float4*>(x + i);
        __half h[4];
        h[0] = __float2half(v.x);
        h[1] = __float2half(v.y);
        h[2] = __float2half(v.z);
        h[3] = __float2half(v.w);
        *reinterpret_cast<uint2*>(xo + i) = *reinterpret_cast<uint2*>(h);
    } else {
        uint32_t idx = (blockIdx.x - XB) * 256u + threadIdx.x;
        int s = 0;
#pragma unroll
        for (int j = 1; j < 8; j++)
            if (idx >= t.s[j].off) s = j;
        const WSeg seg = t.s[s];
        uint32_t i = idx - seg.off;
        uint32_t k = i / seg.N, n = i % seg.N;
        float v = (k < seg.Kreal) ? seg.src[(size_t)k * seg.N + n] : 0.0f;
        w[idx] = __float2half(v);
    }
}

// ---------------------------------------------------------------- mma.sync GEMM
// 256 threads, 8 warps (2 in M x 4 in N). CTA tile (32*MT) x 128, BK = 32.
// A, B single fp16 planes, fp32 accumulate. 4-stage cp.async pipeline with an
// INVARIANT of exactly 3 committed groups in flight at every wait (empty
// commit groups pad when Kc < 3 or past the tail), so wait_group<2> always
// retires precisely the group carrying chunk c.
template <int MT>
__global__ void __launch_bounds__(256, 2)
gemm_mma(const __half* __restrict__ A, const __half* __restrict__ B,
         const float* __restrict__ bias, float* __restrict__ outf,
         __half* __restrict__ O,
         int N, int Kp, int act) {
    constexpr uint32_t BM = 32u * MT;
    constexpr uint32_t A_PLANE = BM * 80u;
    constexpr uint32_t B_PLANE = 8704u;      // 32 rows * 272 B
    constexpr uint32_t STAGE = A_PLANE + B_PLANE;

    extern __shared__ char smem[];
    const uint32_t sb = smem_u32(smem);
    const int tid = threadIdx.x;
    const int lane = tid & 31, warp = tid >> 5;
    const int wm = warp & 1, wn = warp >> 1;
    const int mblock = blockIdx.y, nblock = blockIdx.x;
    const int Kc = Kp >> 5;

    auto issue_body = [&](int c) {
        const uint32_t st_ = sb + (uint32_t)(c & 3) * STAGE;
        const int k0_ = c << 5;
#pragma unroll
        for (int i = tid; i < (int)(BM * 4); i += 256) {
            int row = i >> 2, kc = i & 3;
            size_t go = (size_t)(mblock * BM + row) * Kp + k0_ + kc * 8;
            uint32_t so = st_ + row * 80 + kc * 16;
            cp16(so, A + go);
        }
#pragma unroll
        for (int j = 0; j < 2; j++) {
            int i = tid + j * 256;
            int row = i >> 4, nc = i & 15;
            size_t go = (size_t)(k0_ + row) * N + nblock * 128 + nc * 8;
            uint32_t so = st_ + A_PLANE + row * 272 + nc * 16;
            cp16(so, B + go);
        }
    };

    // prologue: exactly 3 committed groups (empty where c >= Kc)
#pragma unroll
    for (int c = 0; c < 3; c++) {
        if (c < Kc) issue_body(c);
        cp_commit();
    }

    float acc[MT][4][4];
#pragma unroll
    for (int mt = 0; mt < MT; mt++)
#pragma unroll
        for (int nt = 0; nt < 4; nt++)
#pragma unroll
            for (int t = 0; t < 4; t++) acc[mt][nt][t] = 0.0f;

    for (int c = 0; c < Kc; c++) {
        cp_wait2();          // 3 outstanding -> retires group carrying chunk c
        __syncthreads();
        if (c + 3 < Kc) issue_body(c + 3);
        cp_commit();         // keep 3-group invariant (possibly empty)

        const uint32_t st = sb + (uint32_t)(c & 3) * STAGE;
#pragma unroll
        for (int kk = 0; kk < 32; kk += 16) {
            uint32_t bf[4][2];
#pragma unroll
            for (int np = 0; np < 2; np++) {
                int row = kk + (lane & 15);
                int nc = ((wn * 32 + np * 16) >> 3) + (lane >> 4);
                uint32_t bd = st + A_PLANE + row * 272 + nc * 16;
                uint32_t r[4];
                ldsm_x4t(r, bd);
                bf[np * 2][0] = r[0]; bf[np * 2][1] = r[1];
                bf[np * 2 + 1][0] = r[2]; bf[np * 2 + 1][1] = r[3];
            }
#pragma unroll
            for (int mt = 0; mt < MT; mt++) {
                int row = wm * (16 * MT) + mt * 16 + (lane & 15);
                int kc = (kk >> 3) + (lane >> 4);
                uint32_t ad = st + row * 80 + kc * 16;
                uint32_t af[4];
                ldsm_x4(af, ad);
#pragma unroll
                for (int nt = 0; nt < 4; nt++)
                    mma_f16(acc[mt][nt], af, bf[nt]);
            }
        }
    }

    // ---------------- epilogue ----------------
#pragma unroll
    for (int mt = 0; mt < MT; mt++) {
#pragma unroll
        for (int nt = 0; nt < 4; nt++) {
            const int r0 = mblock * BM + wm * (16 * MT) + mt * 16 + (lane >> 2);
            const int cc = nblock * 128 + wn * 32 + nt * 8 + (lane & 3) * 2;
            const float2 bv = *reinterpret_cast<const float2*>(&bias[cc]);
            float v[4];
            v[0] = acc[mt][nt][0] + bv.x;
            v[1] = acc[mt][nt][1] + bv.y;
            v[2] = acc[mt][nt][2] + bv.x;
            v[3] = acc[mt][nt][3] + bv.y;
#pragma unroll
            for (int t = 0; t < 4; t++)
                v[t] = (act == 1) ? (v[t] >= 0.0f ? v[t] : 0.2f * v[t]) : tanhf(v[t]);
            if (outf) {
                *reinterpret_cast<float2*>(&outf[(size_t)r0 * N + cc]) = make_float2(v[0], v[1]);
                *reinterpret_cast<float2*>(&outf[(size_t)(r0 + 8) * N + cc]) = make_float2(v[2], v[3]);
            } else {
#pragma unroll
                for (int rr = 0; rr < 2; rr++) {
                    __half2 hp;
                    hp.x = __float2half(v[rr * 2 + 0]);
                    hp.y = __float2half(v[rr * 2 + 1]);
                    const size_t o = (size_t)(r0 + rr * 8) * N + cc;
                    *reinterpret_cast<__half2*>(&O[o]) = hp;
                }
            }
        }
    }
}

#define SMEM_MT4 (4u * (128u * 80u + 8704u))   // 75776
#define SMEM_MT2 (4u * (64u * 80u + 8704u))    // 55296
#define SMEM_MT1 (4u * (32u * 80u + 8704u))    // 45056

// ---------------------------------------------------------------- quantum circuit
template <int Q>
__device__ __forceinline__ void rot_gate(float (&re)[8], float (&im)[8],
                                         float m00r, float m00i, float m01r, float m01i,
                                         float m10r, float m10i, float m11r, float m11i,
                                         int lane) {
    if constexpr (Q < 3) {
        constexpr int rm = 1 << (2 - Q);
#pragma unroll
        for (int r = 0; r < 8; r++)
            if (!(r & rm)) {
                const int p = r | rm;
                const float ar = re[r], ai = im[r], br = re[p], bi = im[p];
                re[r] = m00r * ar - m00i * ai + m01r * br - m01i * bi;
                im[r] = m00r * ai + m00i * ar + m01r * bi + m01i * br;
                re[p] = m10r * ar - m10i * ai + m11r * br - m11i * bi;
                im[p] = m10r * ai + m10i * ar + m11r * bi + m11i * br;
            }
    } else {
        constexpr int lm = 1 << (7 - Q);
        const bool hi = lane & lm;
#pragma unroll
        for (int r = 0; r < 8; r++) {
            const float pr = __shfl_xor_sync(0xffffffffu, re[r], lm);
            const float pi = __shfl_xor_sync(0xffffffffu, im[r], lm);
            const float ar = re[r], ai = im[r];
            if (!hi) {
                re[r] = m00r * ar - m00i * ai + m01r * pr - m01i * pi;
                im[r] = m00r * ai + m00i * ar + m01r * pi + m01i * pr;
            } else {
                re[r] = m10r * pr - m10i * pi + m11r * ar - m11i * ai;
                im[r] = m10r * pi + m10i * pr + m11r * ai + m11i * ar;
            }
        }
    }
}

template <int C, int T>
__device__ __forceinline__ void cnot_gate(float (&re)[8], float (&im)[8], int lane) {
    if constexpr (C < 3 && T < 3) {
        constexpr int cm = 1 << (2 - C), tm = 1 << (2 - T);
#pragma unroll
        for (int r = 0; r < 8; r++)
            if ((r & cm) && !(r & tm)) {
                const int p = r | tm;
                float t;
                t = re[r]; re[r] = re[p]; re[p] = t;
                t = im[r]; im[r] = im[p]; im[p] = t;
            }
    } else if constexpr (C < 3 && T >= 3) {
        constexpr int cm = 1 << (2 - C), tm = 1 << (7 - T);
#pragma unroll
        for (int r = 0; r < 8; r++)
            if (r & cm) {
                re[r] = __shfl_xor_sync(0xffffffffu, re[r], tm);
                im[r] = __shfl_xor_sync(0xffffffffu, im[r], tm);
            }
    } else if constexpr (C >= 3 && T < 3) {
        constexpr int cm = 1 << (7 - C), tm = 1 << (2 - T);
        const bool act = lane & cm;
#pragma unroll
        for (int r = 0; r < 8; r++)
            if (!(r & tm)) {
                const int p = r | tm;
                const float r0 = act ? re[p] : re[r];
                const float r1 = act ? re[r] : re[p];
                const float i0 = act ? im[p] : im[r];
                const float i1 = act ? im[r] : im[p];
                re[r] = r0; re[p] = r1; im[r] = i0; im[p] = i1;
            }
    } else {
        constexpr int cm = 1 << (7 - C), tm = 1 << (7 - T);
        const int src = (lane & cm) ? (lane ^ tm) : lane;
#pragma unroll
        for (int r = 0; r < 8; r++) {
            re[r] = __shfl_sync(0xffffffffu, re[r], src);
            im[r] = __shfl_sync(0xffffffffu, im[r], src);
        }
    }
}

template <int L>
__device__ __forceinline__ void do_layer(float (&re)[8], float (&im)[8],
                                         const float* __restrict__ sp, int lane) {
#define ROTG(Q) {                                                                   \
        const float phi = sp[(L * 8 + Q) * 3 + 0];                                  \
        const float th  = sp[(L * 8 + Q) * 3 + 1];                                  \
        const float om  = sp[(L * 8 + Q) * 3 + 2];                                  \
        float s, c, sa, ca, sd, cd;                                                 \
        sincosf(0.5f * th, &s, &c);                                                 \
        sincosf(0.5f * (phi + om), &sa, &ca);                                       \
        sincosf(0.5f * (phi - om), &sd, &cd);                                       \
        rot_gate<Q>(re, im, ca * c, -sa * c, -cd * s, -sd * s,                      \
                    cd * s, -sd * s, ca * c, sa * c, lane); }
    ROTG(0) ROTG(1) ROTG(2) ROTG(3) ROTG(4) ROTG(5) ROTG(6) ROTG(7)
#undef ROTG
    cnot_gate<0, (0 + L + 1) % 8>(re, im, lane);
    cnot_gate<1, (1 + L + 1) % 8>(re, im, lane);
    cnot_gate<2, (2 + L + 1) % 8>(re, im, lane);
    cnot_gate<3, (3 + L + 1) % 8>(re, im, lane);
    cnot_gate<4, (4 + L + 1) % 8>(re, im, lane);
    cnot_gate<5, (5 + L + 1) % 8>(re, im, lane);
    cnot_gate<6, (6 + L + 1) % 8>(re, im, lane);
    cnot_gate<7, (7 + L + 1) % 8>(re, im, lane);
}

template <int Q>
__device__ __forceinline__ void measure(const float (&re)[8], const float (&im)[8], int lane,
                                        float& Z, float& X, float& Y) {
    float z = 0.0f, x = 0.0f, y = 0.0f;
    if constexpr (Q < 3) {
        constexpr int rm = 1 << (2 - Q);
#pragma unroll
        for (int r = 0; r < 8; r++) {
            const float ar = re[r], ai = im[r];
            const int p = r ^ rm;
            const float br = re[p], bi = im[p];
            const float sign = (r & rm) ? -1.0f : 1.0f;
            z += sign * (ar * ar + ai * ai);
            x += ar * br + ai * bi;
            y += sign * (ar * bi - ai * br);
        }
    } else {
        constexpr int lm = 1 << (7 - Q);
        const float sign = (lane & lm) ? -1.0f : 1.0f;
#pragma unroll
        for (int r = 0; r < 8; r++) {
            const float ar = re[r], ai = im[r];
            const float br = __shfl_xor_sync(0xffffffffu, ar, lm);
            const float bi = __shfl_xor_sync(0xffffffffu, ai, lm);
            z += sign * (ar * ar + ai * ai);
            x += ar * br + ai * bi;
            y += sign * (ar * bi - ai * br);
        }
    }
#pragma unroll
    for (int o = 16; o > 0; o >>= 1) {
        z += __shfl_xor_sync(0xffffffffu, z, o);
        x += __shfl_xor_sync(0xffffffffu, x, o);
        y += __shfl_xor_sync(0xffffffffu, y, o);
    }
    Z = z; X = x; Y = y;
}

__global__ void __launch_bounds__(256)
quantum_kernel(const float* __restrict__ enc, const float* __restrict__ params,
               __half* __restrict__ mh) {
    __shared__ float sp[144];
    __shared__ float sm[8][32];

    const int tid = threadIdx.x;
    const int lane = tid & 31, w = tid >> 5;
    if (tid < 144) sp[tid] = params[tid];
    __syncthreads();

    const int row = blockIdx.x * 8 + w;

    float re[8], im[8];
    float ss = 0.0f;
#pragma unroll
    for (int r = 0; r < 8; r++) {
        const float v = enc[(size_t)row * 256 + r * 32 + lane];
        re[r] = v; im[r] = 0.0f;
        ss += v * v;
    }
#pragma unroll
    for (int o = 16; o > 0; o >>= 1) ss += __shfl_xor_sync(0xffffffffu, ss, o);
    const float inv = 1.0f / fmaxf(sqrtf(ss), 1e-12f);
#pragma unroll
    for (int r = 0; r < 8; r++) re[r] *= inv;

    do_layer<0>(re, im, sp, lane);
    do_layer<1>(re, im, sp, lane);
    do_layer<2>(re, im, sp, lane);
    do_layer<3>(re, im, sp, lane);
    do_layer<4>(re, im, sp, lane);
    do_layer<5>(re, im, sp, lane);

#define MEAS(Q) {                                                   \
        float Z, X, Y;                                              \
        measure<Q>(re, im, lane, Z, X, Y);                          \
        if (lane == 0) { sm[w][Q] = Z; sm[w][8 + Q] = X; sm[w][16 + Q] = Y; } }
    MEAS(0) MEAS(1) MEAS(2) MEAS(3) MEAS(4) MEAS(5) MEAS(6) MEAS(7)
#undef MEAS
    __syncwarp();

    const float mv = (lane < 24) ? sm[w][lane] : 0.0f;
    mh[(size_t)row * 32 + lane] = __float2half(mv);
}

// ---------------------------------------------------------------- launch
extern "C" void kernel_launch(void* const* d_in, const int* in_sizes, int n_in,
                              void* d_out, int out_size) {
    const float* x          = (const float*)d_in[0];
    const float* ew1        = (const float*)d_in[1];
    const float* eb1        = (const float*)d_in[2];
    const float* ew2        = (const float*)d_in[3];
    const float* eb2        = (const float*)d_in[4];
    const float* ew3        = (const float*)d_in[5];
    const float* eb3        = (const float*)d_in[6];
    const float* dec_params = (const float*)d_in[7];
    const float* dw1        = (const float*)d_in[8];
    const float* db1        = (const float*)d_in[9];
    const float* dw2        = (const float*)d_in[10];
    const float* db2        = (const float*)d_in[11];
    const float* dw3        = (const float*)d_in[12];
    const float* db3        = (const float*)d_in[13];
    const float* dw4        = (const float*)d_in[14];
    const float* db4        = (const float*)d_in[15];
    const float* dw5        = (const float*)d_in[16];
    const float* db5        = (const float*)d_in[17];
    float* out = (float*)d_out;

    __half *a_, *wt_;
    float* enc;
    cudaGetSymbolAddress((void**)&a_, g_act);
    cudaGetSymbolAddress((void**)&wt_, g_wt);
    cudaGetSymbolAddress((void**)&enc, g_enc);

    cudaFuncSetAttribute(gemm_mma<4>, cudaFuncAttributeMaxDynamicSharedMemorySize, SMEM_MT4);
    cudaFuncSetAttribute(gemm_mma<2>, cudaFuncAttributeMaxDynamicSharedMemorySize, SMEM_MT2);
    cudaFuncSetAttribute(gemm_mma<1>, cudaFuncAttributeMaxDynamicSharedMemorySize, SMEM_MT1);

    // ---- conversions (single launch) ----
    WTable wt;
    wt.s[0] = {ew1, W1_OFF, 1024, 2560};
    wt.s[1] = {ew2, W2_OFF, 512, 1024};
    wt.s[2] = {ew3, W3_OFF, 256, 512};
    wt.s[3] = {dw1, W4_OFF, 128, 24};
    wt.s[4] = {dw2, W5_OFF, 256, 128};
    wt.s[5] = {dw3, W6_OFF, 512, 256};
    wt.s[6] = {dw4, W7_OFF, 1024, 512};
    wt.s[7] = {dw5, W8_OFF, 2560, 1024};
    conv_all<<<XB + WB, 256>>>(x, wt, a_ + X_OFF, wt_);

    // ---- encoder ----
    gemm_mma<4><<<dim3(8, 32), 256, SMEM_MT4>>>(a_ + X_OFF, wt_ + W1_OFF,
                                                eb1, nullptr, a_ + H1_OFF, 1024, 2560, 1);
    gemm_mma<2><<<dim3(4, 64), 256, SMEM_MT2>>>(a_ + H1_OFF, wt_ + W2_OFF,
                                                eb2, nullptr, a_ + H2_OFF, 512, 1024, 1);
    gemm_mma<2><<<dim3(2, 64), 256, SMEM_MT2>>>(a_ + H2_OFF, wt_ + W3_OFF,
                                                eb3, enc, nullptr, 256, 512, 2);

    // ---- quantum (one warp per row) ----
    quantum_kernel<<<BATCH / 8, 256>>>(enc, dec_params, a_ + MS_OFF);

    // ---- decoder ----
    gemm_mma<1><<<dim3(1, 128), 256, SMEM_MT1>>>(a_ + MS_OFF, wt_ + W4_OFF,
                                                 db1, nullptr, a_ + D1_OFF, 128, 32, 1);
    gemm_mma<2><<<dim3(2, 64), 256, SMEM_MT2>>>(a_ + D1_OFF, wt_ + W5_OFF,
                                                db2, nullptr, a_ + D2_OFF, 256, 128, 1);
    gemm_mma<2><<<dim3(4, 64), 256, SMEM_MT2>>>(a_ + D2_OFF, wt_ + W6_OFF,
                                                db3, nullptr, a_ + D3_OFF, 512, 256, 1);
    gemm_mma<4><<<dim3(8, 32), 256, SMEM_MT4>>>(a_ + D3_OFF, wt_ + W7_OFF,
                                                db4, nullptr, a_ + D4_OFF, 1024, 512, 1);
    gemm_mma<4><<<dim3(20, 32), 256, SMEM_MT4>>>(a_ + D4_OFF, wt_ + W8_OFF,
                                                 db5, out, nullptr, 2560, 1024, 2);
}